// round 15
// baseline (speedup 1.0000x reference)
#include <cuda_runtime.h>

#define BB 128
#define PP 4096
#define NN 64

// One fused kernel + async memset. Tile = (batch b, point-half h, center-octet g):
// grid = 128*2*8 = 2048. 256 threads = 8 warps; each warp sweeps its own
// 256-point range for the SAME 8 centers (coeffs register-resident),
// 2 points/lane/iter -> 16 independent EX2 chains per warp-iter.
// __launch_bounds__(256,3): the proven occ-3/85-reg scheduling sweet spot.
// Two blocks (h=0,1) contribute to each output via atomicAdd on a zeroed
// buffer: with exactly two commutative contributors the result is
// bit-deterministic regardless of scheduling order.
// q[n](x) = K + a0*x0^2 + b0*x0 + a1*x1^2 + b1*x1,  exp(-dist) = EX2(q)
// Uniform fast path (all 8 centers share a0,a1):
//   q = (K_n + B0_n*x0 + B1_n*x1) + base(x),  base = a0*x0^2 + a1*x1^2
__global__ __launch_bounds__(256, 3) void slayer_fused(
    const float4* __restrict__ batch,    // [B, P/2] of float4 (2 points, D=2)
    const float2* __restrict__ mask,     // [B, P/2] of float2
    const float*  __restrict__ centers,  // [N, D]
    const float*  __restrict__ sharp,    // [N, D]
    float*        __restrict__ out)      // [B, N], pre-zeroed
{
    const int bid  = blockIdx.x;
    const int h    = bid & 1;            // point half
    const int g    = (bid >> 1) & 7;     // centers [8g, 8g+8)
    const int b    = bid >> 4;
    const int tid  = threadIdx.x;
    const int warp = tid >> 5;
    const int lane = tid & 31;
    const int n0   = 8 * g;

    __shared__ float partial[8][8];      // [warp][center]

    const float L = 1.4426950408889634f;  // log2(e)

    // Linear coefficients for 8 centers; uniformity check on a0/a1.
    float B0[8], B1[8], KK[8], acc[8];
    float a00 = 0.0f, a10 = 0.0f;
    bool uniform = true;
#pragma unroll
    for (int j = 0; j < 8; j++) {
        const int n = n0 + j;
        const float c0 = __ldg(centers + 2 * n);
        const float c1 = __ldg(centers + 2 * n + 1);
        const float s0 = __ldg(sharp + 2 * n);
        const float s1 = __ldg(sharp + 2 * n + 1);
        const float a0 = -L * s0 * s0;
        const float a1 = -L * s1 * s1;
        if (j == 0) { a00 = a0; a10 = a1; }
        uniform = uniform && (a0 == a00) && (a1 == a10);
        B0[j] = -2.0f * a0 * c0;
        B1[j] = -2.0f * a1 * c1;
        KK[j] = a0 * c0 * c0 + a1 * c1 * c1;
        acc[j] = 0.0f;
    }

    // This warp's 256-point range: 128 float4 entries.
    const float4* bp = batch + (size_t)b * (PP / 2) + h * (PP / 4)
                       + warp * 128 + lane;
    const float2* mp = mask  + (size_t)b * (PP / 2) + h * (PP / 4)
                       + warp * 128 + lane;

    constexpr int ITERS = 4;   // 4 iters x 32 lanes x 2 points = 256 points

    if (uniform) {
#pragma unroll
        for (int it = 0; it < ITERS; it++) {
            const float4 x = __ldg(bp + it * 32);  // A=(x,y), B=(z,w)
            const float2 m = __ldg(mp + it * 32);

            const float basea = fmaf(a00 * x.x, x.x, (a10 * x.y) * x.y);
            const float baseb = fmaf(a00 * x.z, x.z, (a10 * x.w) * x.w);

#pragma unroll
            for (int j = 0; j < 8; j++) {
                float qa = fmaf(B0[j], x.x, KK[j]);
                qa = fmaf(B1[j], x.y, qa);
                qa += basea;
                float qb = fmaf(B0[j], x.z, KK[j]);
                qb = fmaf(B1[j], x.w, qb);
                qb += baseb;
                float ea, eb;
                asm("ex2.approx.ftz.f32 %0, %1;" : "=f"(ea) : "f"(qa));
                asm("ex2.approx.ftz.f32 %0, %1;" : "=f"(eb) : "f"(qb));
                acc[j] = fmaf(m.x, ea, acc[j]);
                acc[j] = fmaf(m.y, eb, acc[j]);
            }
        }
    } else {
        // General path (cold): full quadratic, 2 passes of 4 centers.
        float A0g[8], A1g[8];
#pragma unroll
        for (int j = 0; j < 8; j++) {
            const int n = n0 + j;
            const float s0 = __ldg(sharp + 2 * n);
            const float s1 = __ldg(sharp + 2 * n + 1);
            A0g[j] = -L * s0 * s0;
            A1g[j] = -L * s1 * s1;
        }
#pragma unroll 2
        for (int it = 0; it < ITERS; it++) {
            const float4 x = __ldg(bp + it * 32);
            const float2 m = __ldg(mp + it * 32);
            const float xa0 = x.x * x.x, xa1 = x.y * x.y;
            const float xb0 = x.z * x.z, xb1 = x.w * x.w;
#pragma unroll
            for (int j = 0; j < 8; j++) {
                float qa = KK[j];
                qa = fmaf(A0g[j], xa0, qa);
                qa = fmaf(B0[j], x.x, qa);
                qa = fmaf(A1g[j], xa1, qa);
                qa = fmaf(B1[j], x.y, qa);
                float qb = KK[j];
                qb = fmaf(A0g[j], xb0, qb);
                qb = fmaf(B0[j], x.z, qb);
                qb = fmaf(A1g[j], xb1, qb);
                qb = fmaf(B1[j], x.w, qb);
                float ea, eb;
                asm("ex2.approx.ftz.f32 %0, %1;" : "=f"(ea) : "f"(qa));
                asm("ex2.approx.ftz.f32 %0, %1;" : "=f"(eb) : "f"(qb));
                acc[j] = fmaf(m.x, ea, acc[j]);
                acc[j] = fmaf(m.y, eb, acc[j]);
            }
        }
    }

    // Reduce over lanes, stash per-warp partials
#pragma unroll
    for (int off = 16; off > 0; off >>= 1) {
#pragma unroll
        for (int j = 0; j < 8; j++)
            acc[j] += __shfl_xor_sync(0xffffffffu, acc[j], off);
    }
    if (lane == 0) {
#pragma unroll
        for (int j = 0; j < 8; j++)
            partial[warp][j] = acc[j];
    }

    __syncthreads();

    // Combine 8 warp partials -> one atomic contribution per output.
    // Exactly 2 blocks (h=0,1) hit each output; float add is commutative,
    // so the result is identical for either arrival order.
    if (tid < 8) {
        float v = 0.0f;
#pragma unroll
        for (int w = 0; w < 8; w++)
            v += partial[w][tid];
        atomicAdd(out + b * NN + n0 + tid, v);
    }
}

extern "C" void kernel_launch(void* const* d_in, const int* in_sizes, int n_in,
                              void* d_out, int out_size) {
    const float* batch   = (const float*)d_in[0];   // [B,P,D] f32
    const float* mask    = (const float*)d_in[1];   // [B,P]   f32
    const float* centers = (const float*)d_in[2];   // [N,D]   f32
    const float* sharp   = (const float*)d_in[3];   // [N,D]   f32
    float* out = (float*)d_out;                     // [B,N]   f32

    cudaMemsetAsync(out, 0, (size_t)out_size * sizeof(float));
    slayer_fused<<<BB * 16, 256>>>((const float4*)batch, (const float2*)mask,
                                   centers, sharp, out);
}